// round 16
// baseline (speedup 1.0000x reference)
#include <cuda_runtime.h>
#include <cuda_bf16.h>
#include <cstdint>

#define B_  8
#define C_  256
#define HW_ 4096
#define M_  512

// ---------------- device scratch ----------------
__device__ float g_IG[B_ * C_];
__device__ float g_P[M_ * C_];                    // P[m][o] = sum_c W2[o][c]*mem[m][c]
__device__ float g_x[(size_t)B_ * C_ * HW_];      // pre-depthwise activations
__device__ unsigned char g_memB[8 * 32768];       // B fragment images of memory, bf16 HIGH only
__device__ unsigned char g_fwB[B_ * 4 * 65536];   // B fragment images: gated fusion_w split h/l (per batch)

// ---------------- helpers ----------------
static __device__ __forceinline__ void mma_bf16(float* c,
    uint32_t a0, uint32_t a1, uint32_t a2, uint32_t a3, uint32_t b0, uint32_t b1) {
    asm("mma.sync.aligned.m16n8k16.row.col.f32.bf16.bf16.f32 "
        "{%0,%1,%2,%3}, {%4,%5,%6,%7}, {%8,%9}, {%0,%1,%2,%3};"
        : "+f"(c[0]), "+f"(c[1]), "+f"(c[2]), "+f"(c[3])
        : "r"(a0), "r"(a1), "r"(a2), "r"(a3), "r"(b0), "r"(b1));
}
static __device__ __forceinline__ void split_bf16(float v, unsigned short& hb, unsigned short& lb) {
    __nv_bfloat16 h = __float2bfloat16_rn(v);
    __nv_bfloat16 l = __float2bfloat16_rn(v - __bfloat162float(h));
    hb = *(unsigned short*)&h;
    lb = *(unsigned short*)&l;
}
static __device__ __forceinline__ uint32_t pk(unsigned short a, unsigned short b) {
    return (uint32_t)a | ((uint32_t)b << 16);
}
static __device__ __forceinline__ bool better(float v, int i, float v2, int i2) {
    return v > v2 || (v == v2 && i < i2);
}
static __device__ __forceinline__ void ins4(float* tv, int* ti, float v, int i) {
    if (better(v, i, tv[3], ti[3])) {
        if (better(v, i, tv[2], ti[2])) {
            tv[3] = tv[2]; ti[3] = ti[2];
            if (better(v, i, tv[1], ti[1])) {
                tv[2] = tv[1]; ti[2] = ti[1];
                if (better(v, i, tv[0], ti[0])) { tv[1] = tv[0]; ti[1] = ti[0]; tv[0] = v; ti[0] = i; }
                else { tv[1] = v; ti[1] = i; }
            } else { tv[2] = v; ti[2] = i; }
        } else { tv[3] = v; ti[3] = i; }
    }
}

// ---------------- K1: merged pre-pass (mean | memB prep | P matrix), all independent ----------------
__global__ void k_pre(const float* __restrict__ img, const float* __restrict__ mem,
                      const float* __restrict__ fw) {
    __shared__ float shr[256];
    int bid = blockIdx.x;
    int t = threadIdx.x;
    if (bid < 2048) {
        // spatial mean per (b,c)
        const float4* p = (const float4*)(img + (size_t)bid * HW_);
        float s = 0.f;
        for (int i = t; i < HW_ / 4; i += 256) {
            float4 v = p[i];
            s += (v.x + v.y) + (v.z + v.w);
        }
        shr[t] = s;
        __syncthreads();
        for (int st = 128; st > 0; st >>= 1) {
            if (t < st) shr[t] += shr[t + st];
            __syncthreads();
        }
        if (t == 0) g_IG[bid] = shr[0] * (1.f / (float)HW_);
    } else if (bid < 2080) {
        // memory -> h-only B fragment images
        int u = (bid - 2048) * 256 + t;    // 8192 = 512 m x 16 ks
        int ks = u >> 9;
        int m  = u & 511;
        const float* mr = mem + (size_t)m * C_ + ks * 16;
        unsigned short hs[16], ls[16];
        #pragma unroll
        for (int kin = 0; kin < 16; kin++) split_bf16(mr[kin], hs[kin], ls[kin]);
        int ch = m >> 6, rr = m & 63, nt = rr >> 3, nn = rr & 7;
        uint2* dst = (uint2*)(g_memB + ch * 32768) + (nt * 16 + ks) * 32 + nn * 4;
        #pragma unroll
        for (int j = 0; j < 4; j++)
            dst[j] = make_uint2(pk(hs[2*j], hs[2*j+1]), pk(hs[8+2*j], hs[8+2*j+1]));
    } else {
        // P[m][o] = W2[o,:] . mem[m,:]
        int m = bid - 2080, o = t;
        shr[o] = mem[(size_t)m * C_ + o];
        __syncthreads();
        const float* wr = fw + (size_t)o * 512 + 256;
        float a = 0.f;
        for (int c = 0; c < C_; c += 4) {
            float4 w4 = *(const float4*)(wr + c);
            a += w4.x * shr[c] + w4.y * shr[c + 1] + w4.z * shr[c + 2] + w4.w * shr[c + 3];
        }
        g_P[m * C_ + o] = a;
    }
}

// ---------------- K2: gate chain fused (scores+softmax | gate slice | gated-fw fragments) ----------------
// grid 64 = 8 batches x 8 channel-slices of 32; each block redundantly computes scores/softmax.
__global__ void __launch_bounds__(256) k_gate(const float* __restrict__ mem,
                                              const float* __restrict__ fw) {
    __shared__ float ig[C_];
    __shared__ float sc[M_];
    __shared__ float red[256];
    __shared__ float part[8][33];
    __shared__ float gts[32];
    int b  = blockIdx.x >> 3;
    int cs = blockIdx.x & 7;
    int t  = threadIdx.x;

    ig[t] = g_IG[b * C_ + t];
    __syncthreads();

    // scores: 2 per thread (m = t, t+256)
    #pragma unroll
    for (int r = 0; r < 2; r++) {
        int m = t + r * 256;
        const float* mr = mem + (size_t)m * C_;
        float a = 0.f;
        for (int c = 0; c < C_; c += 4) {
            float4 mv = *(const float4*)(mr + c);
            a += ig[c] * mv.x + ig[c + 1] * mv.y + ig[c + 2] * mv.z + ig[c + 3] * mv.w;
        }
        sc[m] = a;
    }
    __syncthreads();
    red[t] = fmaxf(sc[t], sc[t + 256]);
    __syncthreads();
    for (int st = 128; st > 0; st >>= 1) {
        if (t < st) red[t] = fmaxf(red[t], red[t + st]);
        __syncthreads();
    }
    float mx = red[0];
    __syncthreads();
    float e0 = expf(sc[t] - mx), e1 = expf(sc[t + 256] - mx);
    sc[t] = e0; sc[t + 256] = e1;
    red[t] = e0 + e1;
    __syncthreads();
    for (int st = 128; st > 0; st >>= 1) {
        if (t < st) red[t] += red[t + st];
        __syncthreads();
    }
    float inv = 1.f / red[0];
    __syncthreads();

    // gate slice: c = cs*32 + lane, 8 m-groups of 64
    {
        int c = cs * 32 + (t & 31);
        int mg = t >> 5;
        const float* mp = mem + (size_t)(mg * 64) * C_ + c;
        float acc = 0.f;
        #pragma unroll 8
        for (int m = 0; m < 64; m++) acc += sc[mg * 64 + m] * mp[(size_t)m * C_];
        part[mg][t & 31] = acc;
    }
    __syncthreads();
    if (t < 32) {
        float s = 0.f;
        #pragma unroll
        for (int g = 0; g < 8; g++) s += part[g][t];
        s = s * inv + ig[cs * 32 + t];
        gts[t] = 1.f / (1.f + expf(-s));
    }
    __syncthreads();

    // gated-fw fragment images for ks = 2cs, 2cs+1 (512 units: 2 per thread)
    #pragma unroll
    for (int u0 = 0; u0 < 2; u0++) {
        int u = t + u0 * 256;
        int r = u & 255, ksl = u >> 8;
        int ks = cs * 2 + ksl;
        const float* wr = fw + (size_t)r * 512 + ks * 16;
        unsigned short hs[16], ls[16];
        #pragma unroll
        for (int kin = 0; kin < 16; kin++)
            split_bf16(wr[kin] * gts[ksl * 16 + kin], hs[kin], ls[kin]);
        int ch = r >> 6, rr = r & 63, nt = rr >> 3, nn = rr & 7;
        uint4* dst = (uint4*)(g_fwB + (b * 4 + ch) * 65536) + (nt * 16 + ks) * 32 + nn * 4;
        #pragma unroll
        for (int j = 0; j < 4; j++)
            dst[j] = make_uint4(pk(hs[2*j], hs[2*j+1]), pk(hs[8+2*j], hs[8+2*j+1]),
                                pk(ls[2*j], ls[2*j+1]), pk(ls[8+2*j], ls[8+2*j+1]));
    }
}

// ---------------- K3: main fused kernel (R9 version, measured 171us / 1.5e-5) ----------------
#define OFF_AL 73728
#define OFF_B  147456
#define OFF_SM 212992
#define SMEM_MAIN 220160
#define NCHUNK 12

#define UPD2(val, idx) do { float _v = (val); \
    if (_v > cv0) { cv1 = cv0; ci1 = ci0; cv0 = _v; ci0 = (idx); } \
    else if (_v > cv1) { cv1 = _v; ci1 = (idx); } } while (0)

static __device__ __forceinline__ uint32_t apad(int s) {
    return ((uint32_t)s << 4) + (((uint32_t)s >> 3) << 4);
}

// score chunk: 1-pass bf16 (h only), B slots = uint2
static __device__ __forceinline__ void chunk_mma_s(const unsigned char* sm,
                                                   int wr, int wc, int ln, float acc[4][4]) {
    const uint2* Bfr = (const uint2*)(sm + OFF_B);
    const int sA = wr * 512 + ln;
    #pragma unroll
    for (int ks = 0; ks < 16; ks++) {
        uint4 ah = *(const uint4*)(sm + apad(sA + ks * 32));
        #pragma unroll
        for (int nt = 0; nt < 4; nt++) {
            uint2 bv = Bfr[((wc * 4 + nt) * 16 + ks) * 32 + ln];
            mma_bf16(acc[nt], ah.x, ah.y, ah.z, ah.w, bv.x, bv.y);
        }
    }
}
// fusion chunk: 3-pass split bf16, B slots = uint4
static __device__ __forceinline__ void chunk_mma_f(const unsigned char* sm,
                                                   int wr, int wc, int ln, float acc[4][4]) {
    const uint4* Bfr = (const uint4*)(sm + OFF_B);
    const int sA = wr * 512 + ln;
    #pragma unroll
    for (int ks = 0; ks < 16; ks++) {
        int s = sA + ks * 32;
        uint4 ah = *(const uint4*)(sm + apad(s));
        uint4 al = *(const uint4*)(sm + OFF_AL + apad(s));
        #pragma unroll
        for (int nt = 0; nt < 4; nt++) {
            uint4 bv = Bfr[((wc * 4 + nt) * 16 + ks) * 32 + ln];
            mma_bf16(acc[nt], ah.x, ah.y, ah.z, ah.w, bv.x, bv.y);
            mma_bf16(acc[nt], ah.x, ah.y, ah.z, ah.w, bv.z, bv.w);
            mma_bf16(acc[nt], al.x, al.y, al.z, al.w, bv.x, bv.y);
        }
    }
}

__global__ void __launch_bounds__(512, 1) k_main(
    const float* __restrict__ img, const float* __restrict__ mem, const float* __restrict__ fb)
{
    extern __shared__ unsigned char sm[];
    const int t  = threadIdx.x;
    const int b  = blockIdx.x >> 5;
    const int p0 = (blockIdx.x & 31) * 128;
    const int w  = t >> 5;
    const int ln = t & 31;
    const int wr = w >> 1;
    const int wc = w & 1;

    float* A0s = (float*)(sm + OFF_SM);
    float* A1s = (float*)(sm + OFF_SM + 512);
    int*   I0s = (int*)  (sm + OFF_SM + 1024);
    int*   I1s = (int*)  (sm + OFF_SM + 1536);
    float* bS  = (float*)(sm + OFF_SM + 2048);
    int*   cnd = (int*)  (sm + OFF_SM + 3072);   // [128 px][8 cand]

    uint4 st[8];
    uint4* Bd = (uint4*)(sm + OFF_B);

    // LDG chunk 0 (score, 32KB)
    {
        const uint4* src = (const uint4*)g_memB;
        #pragma unroll
        for (int i = 0; i < 4; i++) st[i] = src[t + i * 512];
    }

    // ---- stage A: split bf16 h/l into padded fragment layout ----
    {
        const float* ib = img + (size_t)b * C_ * HW_ + p0;
        #pragma unroll
        for (int u0 = 0; u0 < 2; u0++) {
            int u = t + u0 * 512;
            int rp = u & 63, ks = u >> 6;
            int pxl = (rp >> 3) * 16 + (rp & 7);
            const float* ibc = ib + (size_t)(ks * 16) * HW_;
            unsigned short hlo[16], llo[16], hhi[16], lhi[16];
            #pragma unroll
            for (int kin = 0; kin < 16; kin++) {
                split_bf16(ibc[(size_t)kin * HW_ + pxl],     hlo[kin], llo[kin]);
                split_bf16(ibc[(size_t)kin * HW_ + pxl + 8], hhi[kin], lhi[kin]);
            }
            int s0 = ((rp >> 3) * 16 + ks) * 32 + (rp & 7) * 4;
            #pragma unroll
            for (int j = 0; j < 4; j++) {
                uint32_t ap = apad(s0 + j);
                *(uint4*)(sm + ap) =
                    make_uint4(pk(hlo[2*j], hlo[2*j+1]), pk(hhi[2*j], hhi[2*j+1]),
                               pk(hlo[8+2*j], hlo[8+2*j+1]), pk(hhi[8+2*j], hhi[8+2*j+1]));
                *(uint4*)(sm + OFF_AL + ap) =
                    make_uint4(pk(llo[2*j], llo[2*j+1]), pk(lhi[2*j], lhi[2*j+1]),
                               pk(llo[8+2*j], llo[8+2*j+1]), pk(lhi[8+2*j], lhi[8+2*j+1]));
            }
        }
    }
    if (t < 256) bS[t] = fb[t];

    // STS chunk 0, LDG chunk 1
    #pragma unroll
    for (int i = 0; i < 4; i++) Bd[t + i * 512] = st[i];
    {
        const uint4* src = (const uint4*)(g_memB + 32768);
        #pragma unroll
        for (int i = 0; i < 4; i++) st[i] = src[t + i * 512];
    }
    __syncthreads();

    // per-(lane,wc) top-4 candidates, 2 pixel slots
    float tv[2][4];
    int   ti[2][4];
    #pragma unroll
    for (int s = 0; s < 2; s++)
        #pragma unroll
        for (int j = 0; j < 4; j++) { tv[s][j] = -3.402823466e38f; ti[s][j] = 0; }

    for (int n = 0; n < NCHUNK; n++) {
        float acc[4][4];
        #pragma unroll
        for (int nt = 0; nt < 4; nt++)
            #pragma unroll
            for (int q = 0; q < 4; q++) acc[nt][q] = 0.f;

        if (n < 8) chunk_mma_s(sm, wr, wc, ln, acc);
        else       chunk_mma_f(sm, wr, wc, ln, acc);

        if (n < 8) {
            // chunk-local top-2 per slot, then merge into persistent top-4
            #pragma unroll
            for (int s = 0; s < 2; s++) {
                float cv0 = -3.402823466e38f, cv1 = -3.402823466e38f;
                int ci0 = 0, ci1 = 0;
                #pragma unroll
                for (int nt = 0; nt < 4; nt++) {
                    int mi = n * 64 + (wc * 4 + nt) * 8 + (ln & 3) * 2;
                    UPD2(acc[nt][s * 2 + 0], mi);
                    UPD2(acc[nt][s * 2 + 1], mi + 1);
                }
                ins4(tv[s], ti[s], cv0, ci0);
                ins4(tv[s], ti[s], cv1, ci1);
            }
            if (n == 7) {
                // merge top-4 across the 4 lanes sharing each pixel (same wc), publish candidates
                #pragma unroll
                for (int s = 0; s < 2; s++) {
                    #pragma unroll
                    for (int d = 1; d <= 2; d <<= 1) {
                        float pv[4]; int pi[4];
                        #pragma unroll
                        for (int j = 0; j < 4; j++) {
                            pv[j] = __shfl_xor_sync(0xFFFFFFFFu, tv[s][j], d);
                            pi[j] = __shfl_xor_sync(0xFFFFFFFFu, ti[s][j], d);
                        }
                        #pragma unroll
                        for (int j = 0; j < 4; j++) ins4(tv[s], ti[s], pv[j], pi[j]);
                    }
                    if ((ln & 3) == 0) {
                        int px = wr * 16 + s * 8 + (ln >> 2);
                        int* cp = cnd + px * 8 + wc * 4;
                        cp[0] = ti[s][0]; cp[1] = ti[s][1]; cp[2] = ti[s][2]; cp[3] = ti[s][3];
                    }
                }
            }
        } else {
            // fusion epilogue
            int oc0 = (n - 8) * 64;
            #pragma unroll
            for (int hf = 0; hf < 2; hf++) {
                int r = wr * 16 + hf * 8 + (ln >> 2);
                float a0 = A0s[r], a1 = A1s[r];
                const float* P0 = g_P + (size_t)I0s[r] * C_ + oc0;
                const float* P1 = g_P + (size_t)I1s[r] * C_ + oc0;
                float* xo = g_x + ((size_t)b * C_ + oc0) * HW_ + p0 + r;
                #pragma unroll
                for (int nt = 0; nt < 4; nt++) {
                    int ocl = wc * 32 + nt * 8 + (ln & 3) * 2;
                    float2 q0 = *(const float2*)(P0 + ocl);
                    float2 q1 = *(const float2*)(P1 + ocl);
                    float vx = acc[nt][hf * 2 + 0] + a0 * q0.x + a1 * q1.x + bS[oc0 + ocl];
                    float vy = acc[nt][hf * 2 + 1] + a0 * q0.y + a1 * q1.y + bS[oc0 + ocl + 1];
                    vx = (vx > 0.f) ? vx : 0.2f * vx;
                    vy = (vy > 0.f) ? vy : 0.2f * vy;
                    xo[(size_t)ocl * HW_] = vx;
                    xo[(size_t)(ocl + 1) * HW_] = vy;
                }
            }
        }
        __syncthreads();

        // stage B(n+1) from regs, LDG B(n+2)
        if (n < NCHUNK - 1) {
            if (n + 1 < 8) {
                #pragma unroll
                for (int i = 0; i < 4; i++) Bd[t + i * 512] = st[i];
            } else {
                #pragma unroll
                for (int i = 0; i < 8; i++) Bd[t + i * 512] = st[i];
            }
            if (n < NCHUNK - 2) {
                int nn = n + 2;
                if (nn < 8) {
                    const uint4* src = (const uint4*)(g_memB + nn * 32768);
                    #pragma unroll
                    for (int i = 0; i < 4; i++) st[i] = src[t + i * 512];
                } else {
                    const uint4* src = (const uint4*)(g_fwB + (b * 4 + (nn - 8)) * 65536);
                    #pragma unroll
                    for (int i = 0; i < 8; i++) st[i] = src[t + i * 512];
                }
            }
        }
        __syncthreads();

        if (n == 7) {
            // ---- rescore: warp w owns pixels [8w, 8w+8); lanes split the 256-c dot ----
            const int ks2 = ln >> 1, h = ln & 1;
            const int pxb = w * 8;
            #pragma unroll 1
            for (int pi = 0; pi < 8; pi++) {
                int px = pxb + pi;
                int mtg = px >> 4, r = px & 15;
                int sb = (mtg * 16 + ks2) * 32 + (r & 7) * 4;
                uint32_t wo = (uint32_t)((h * 2 + (r >> 3)) * 4);
                float aev[4], aov[4];
                #pragma unroll
                for (int q = 0; q < 4; q++) {
                    uint32_t ap = apad(sb + q) + wo;
                    uint32_t wh = *(const uint32_t*)(sm + ap);
                    uint32_t wl = *(const uint32_t*)(sm + OFF_AL + ap);
                    aev[q] = __uint_as_float(wh << 16) + __uint_as_float(wl << 16);
                    aov[q] = __uint_as_float(wh & 0xFFFF0000u) + __uint_as_float(wl & 0xFFFF0000u);
                }
                const int* cp = cnd + px * 8;
                int   mi[8];
                float s[8];
                #pragma unroll
                for (int j = 0; j < 8; j++) {
                    mi[j] = cp[j];
                    const float4* rp = (const float4*)(mem + (size_t)mi[j] * C_ + ln * 8);
                    float4 b0 = rp[0], b1 = rp[1];
                    s[j] = aev[0] * b0.x + aov[0] * b0.y + aev[1] * b0.z + aov[1] * b0.w
                         + aev[2] * b1.x + aov[2] * b1.y + aev[3] * b1.z + aov[3] * b1.w;
                }
                #pragma unroll
                for (int d = 16; d; d >>= 1)
                    #pragma unroll
                    for (int j = 0; j < 8; j++)
                        s[j] += __shfl_xor_sync(0xFFFFFFFFu, s[j], d);
                float t0 = s[0], t1 = -3.402823466e38f;
                int   e0 = mi[0], e1 = 0;
                #pragma unroll
                for (int j = 1; j < 8; j++) {
                    if (better(s[j], mi[j], t0, e0)) { t1 = t0; e1 = e0; t0 = s[j]; e0 = mi[j]; }
                    else if (better(s[j], mi[j], t1, e1)) { t1 = s[j]; e1 = mi[j]; }
                }
                if (ln == 0) {
                    float e = expf(t1 - t0);
                    float a0 = 1.f / (1.f + e);
                    A0s[px] = a0; A1s[px] = e * a0; I0s[px] = e0; I1s[px] = e1;
                }
            }
            __syncthreads();
        }
    }
}

// ---------------- K4: depthwise dilated 3x3 (d=2) + bias + leaky ----------------
__global__ void k_dw(const float* __restrict__ dw, const float* __restrict__ db,
                     float* __restrict__ out) {
    __shared__ float sx[4096];
    __shared__ float w[9];
    int bc = blockIdx.x;
    int c = bc & 255;
    int t = threadIdx.x;
    const float4* x4 = (const float4*)(g_x + (size_t)bc * HW_);
    float4* s4 = (float4*)sx;
    for (int i = t; i < 1024; i += 256) s4[i] = x4[i];
    if (t < 9) w[t] = dw[c * 9 + t];
    __syncthreads();
    float bias = db[c];
    for (int p = t; p < 4096; p += 256) {
        int y = p >> 6, x = p & 63;
        float s = bias;
        #pragma unroll
        for (int ky = 0; ky < 3; ky++) {
            int iy = y + 2 * ky - 2;
            if ((unsigned)iy < 64u) {
                #pragma unroll
                for (int kx = 0; kx < 3; kx++) {
                    int ix = x + 2 * kx - 2;
                    if ((unsigned)ix < 64u) s += w[ky * 3 + kx] * sx[(iy << 6) + ix];
                }
            }
        }
        out[(size_t)bc * HW_ + p] = (s > 0.f) ? s : 0.2f * s;
    }
}

extern "C" void kernel_launch(void* const* d_in, const int* in_sizes, int n_in,
                              void* d_out, int out_size) {
    const float* img = (const float*)d_in[0];
    const float* mem = (const float*)d_in[1];
    const float* fw  = (const float*)d_in[2];
    const float* fb  = (const float*)d_in[3];
    const float* dw  = (const float*)d_in[4];
    const float* db  = (const float*)d_in[5];
    float* out = (float*)d_out;

    cudaFuncSetAttribute(k_main, cudaFuncAttributeMaxDynamicSharedMemorySize, SMEM_MAIN);

    k_pre<<<2048 + 32 + 512, 256>>>(img, mem, fw);
    k_gate<<<B_ * 8, 256>>>(mem, fw);
    k_main<<<B_ * (HW_ / 128), 512, SMEM_MAIN>>>(img, mem, fb);
    k_dw<<<B_ * C_, 256>>>(dw, db, out);
}

// round 17
// speedup vs baseline: 1.0710x; 1.0710x over previous
#include <cuda_runtime.h>
#include <cuda_bf16.h>
#include <cstdint>

#define B_  8
#define C_  256
#define HW_ 4096
#define M_  512

// ---------------- device scratch ----------------
__device__ float g_IG[B_ * C_];
__device__ float g_sc[B_ * M_];                   // normalized softmax weights
__device__ float g_gate[B_ * C_];
__device__ float g_P[M_ * C_];                    // P[m][o] = sum_c W2[o][c]*mem[m][c]
__device__ float g_x[(size_t)B_ * C_ * HW_];      // pre-depthwise activations
__device__ unsigned char g_memB[8 * 32768];       // B fragment images of memory, bf16 HIGH only
__device__ unsigned char g_fwB[B_ * 4 * 65536];   // B fragment images: gated fusion_w split h/l (per batch)

// ---------------- helpers ----------------
static __device__ __forceinline__ void mma_bf16(float* c,
    uint32_t a0, uint32_t a1, uint32_t a2, uint32_t a3, uint32_t b0, uint32_t b1) {
    asm("mma.sync.aligned.m16n8k16.row.col.f32.bf16.bf16.f32 "
        "{%0,%1,%2,%3}, {%4,%5,%6,%7}, {%8,%9}, {%0,%1,%2,%3};"
        : "+f"(c[0]), "+f"(c[1]), "+f"(c[2]), "+f"(c[3])
        : "r"(a0), "r"(a1), "r"(a2), "r"(a3), "r"(b0), "r"(b1));
}
static __device__ __forceinline__ void split_bf16(float v, unsigned short& hb, unsigned short& lb) {
    __nv_bfloat16 h = __float2bfloat16_rn(v);
    __nv_bfloat16 l = __float2bfloat16_rn(v - __bfloat162float(h));
    hb = *(unsigned short*)&h;
    lb = *(unsigned short*)&l;
}
static __device__ __forceinline__ uint32_t pk(unsigned short a, unsigned short b) {
    return (uint32_t)a | ((uint32_t)b << 16);
}
static __device__ __forceinline__ bool better(float v, int i, float v2, int i2) {
    return v > v2 || (v == v2 && i < i2);
}
static __device__ __forceinline__ void ins4(float* tv, int* ti, float v, int i) {
    if (better(v, i, tv[3], ti[3])) {
        if (better(v, i, tv[2], ti[2])) {
            tv[3] = tv[2]; ti[3] = ti[2];
            if (better(v, i, tv[1], ti[1])) {
                tv[2] = tv[1]; ti[2] = ti[1];
                if (better(v, i, tv[0], ti[0])) { tv[1] = tv[0]; ti[1] = ti[0]; tv[0] = v; ti[0] = i; }
                else { tv[1] = v; ti[1] = i; }
            } else { tv[2] = v; ti[2] = i; }
        } else { tv[3] = v; ti[3] = i; }
    }
}

// ---------------- K1a: per-(b,c) spatial mean ----------------
__global__ void k_mean(const float* __restrict__ img) {
    __shared__ float red[256];
    int bc = blockIdx.x;
    const float4* p = (const float4*)(img + (size_t)bc * HW_);
    float s = 0.f;
    for (int i = threadIdx.x; i < HW_ / 4; i += 256) {
        float4 v = p[i];
        s += (v.x + v.y) + (v.z + v.w);
    }
    red[threadIdx.x] = s;
    __syncthreads();
    for (int st = 128; st > 0; st >>= 1) {
        if (threadIdx.x < st) red[threadIdx.x] += red[threadIdx.x + st];
        __syncthreads();
    }
    if (threadIdx.x == 0) g_IG[bc] = red[0] * (1.f / (float)HW_);
}

// ---------------- K1b: memory -> h-only B fragment images ----------------
__global__ void k_prep(const float* __restrict__ mem) {
    int u = blockIdx.x * 256 + threadIdx.x;   // 8192 = 512 m x 16 ks
    int ks = u >> 9;
    int m  = u & 511;
    const float* mr = mem + (size_t)m * C_ + ks * 16;
    unsigned short hs[16], ls[16];
    #pragma unroll
    for (int kin = 0; kin < 16; kin++) split_bf16(mr[kin], hs[kin], ls[kin]);
    int ch = m >> 6, rr = m & 63, nt = rr >> 3, nn = rr & 7;
    uint2* dst = (uint2*)(g_memB + ch * 32768) + (nt * 16 + ks) * 32 + nn * 4;
    #pragma unroll
    for (int j = 0; j < 4; j++)
        dst[j] = make_uint2(pk(hs[2*j], hs[2*j+1]), pk(hs[8+2*j], hs[8+2*j+1]));
}

// ---------------- K1c: P[m][o] = W2[o,:] . mem[m,:] ----------------
__global__ void k_pmat(const float* __restrict__ mem, const float* __restrict__ fw) {
    __shared__ float row[C_];
    int m = blockIdx.x, o = threadIdx.x;
    row[o] = mem[(size_t)m * C_ + o];
    __syncthreads();
    const float* wr = fw + (size_t)o * 512 + 256;
    float a = 0.f;
    for (int c = 0; c < C_; c += 4) {
        float4 w4 = *(const float4*)(wr + c);
        a += w4.x * row[c] + w4.y * row[c + 1] + w4.z * row[c + 2] + w4.w * row[c + 3];
    }
    g_P[m * C_ + o] = a;
}

// ---------------- K2a: scores + softmax -> normalized weights ----------------
__global__ void __launch_bounds__(512) k_gsc(const float* __restrict__ mem) {
    __shared__ float ig[C_];
    __shared__ float red[M_];
    int b = blockIdx.x, t = threadIdx.x;
    if (t < 256) ig[t] = g_IG[b * C_ + t];
    __syncthreads();
    const float* mr = mem + (size_t)t * C_;
    float a = 0.f;
    for (int c = 0; c < C_; c += 4) {
        float4 mv = *(const float4*)(mr + c);
        a += ig[c] * mv.x + ig[c + 1] * mv.y + ig[c + 2] * mv.z + ig[c + 3] * mv.w;
    }
    red[t] = a;
    __syncthreads();
    for (int st = 256; st > 0; st >>= 1) {
        if (t < st) red[t] = fmaxf(red[t], red[t + st]);
        __syncthreads();
    }
    float mx = red[0];
    __syncthreads();
    float e = expf(a - mx);
    red[t] = e;
    __syncthreads();
    for (int st = 256; st > 0; st >>= 1) {
        if (t < st) red[t] += red[t + st];
        __syncthreads();
    }
    g_sc[b * M_ + t] = e / red[0];
}

// ---------------- K2b: gate accumulation (64 blocks) ----------------
__global__ void k_gacc(const float* __restrict__ mem) {
    __shared__ float part[8][33];
    __shared__ float scs[M_];
    int b  = blockIdx.x >> 3;
    int cs = blockIdx.x & 7;
    int t  = threadIdx.x;
    int c  = cs * 32 + (t & 31);
    int mg = t >> 5;                 // 8 m-groups of 64
    scs[t] = g_sc[b * M_ + t];
    scs[t + 256] = g_sc[b * M_ + t + 256];
    __syncthreads();
    const float* mp = mem + (size_t)(mg * 64) * C_ + c;
    float acc = 0.f;
    #pragma unroll 8
    for (int m = 0; m < 64; m++) acc += scs[mg * 64 + m] * mp[(size_t)m * C_];
    part[mg][t & 31] = acc;
    __syncthreads();
    if (t < 32) {
        float s = 0.f;
        #pragma unroll
        for (int g = 0; g < 8; g++) s += part[g][t];
        s += g_IG[b * C_ + c];
        g_gate[b * C_ + c] = 1.f / (1.f + expf(-s));
    }
}

// ---------------- K2w: gated fusion_w -> split h/l B fragment images per batch ----------------
__global__ void k_prepw(const float* __restrict__ fw) {
    int u = blockIdx.x * 256 + threadIdx.x;   // 32768 = 16 ks x 8 b x 256 r
    int ks = u >> 11;
    int b  = (u >> 8) & 7;
    int r  = u & 255;
    const float* wr = fw + (size_t)r * 512 + ks * 16;
    const float* gt = g_gate + b * C_ + ks * 16;
    unsigned short hs[16], ls[16];
    #pragma unroll
    for (int kin = 0; kin < 16; kin++) split_bf16(wr[kin] * gt[kin], hs[kin], ls[kin]);
    int ch = r >> 6, rr = r & 63, nt = rr >> 3, nn = rr & 7;
    uint4* dst = (uint4*)(g_fwB + (b * 4 + ch) * 65536) + (nt * 16 + ks) * 32 + nn * 4;
    #pragma unroll
    for (int j = 0; j < 4; j++)
        dst[j] = make_uint4(pk(hs[2*j], hs[2*j+1]), pk(hs[8+2*j], hs[8+2*j+1]),
                            pk(ls[2*j], ls[2*j+1]), pk(ls[8+2*j], ls[8+2*j+1]));
}

// ---------------- K3: main fused kernel (1-chunk lookahead, reduced reg pressure) ----------------
#define OFF_AL 73728
#define OFF_B  147456
#define OFF_SM 212992
#define SMEM_MAIN 220160
#define NCHUNK 12

#define UPD2(val, idx) do { float _v = (val); \
    if (_v > cv0) { cv1 = cv0; ci1 = ci0; cv0 = _v; ci0 = (idx); } \
    else if (_v > cv1) { cv1 = _v; ci1 = (idx); } } while (0)

static __device__ __forceinline__ uint32_t apad(int s) {
    return ((uint32_t)s << 4) + (((uint32_t)s >> 3) << 4);
}

// score chunk: 1-pass bf16 (h only), B slots = uint2
static __device__ __forceinline__ void chunk_mma_s(const unsigned char* sm,
                                                   int wr, int wc, int ln, float acc[4][4]) {
    const uint2* Bfr = (const uint2*)(sm + OFF_B);
    const int sA = wr * 512 + ln;
    #pragma unroll
    for (int ks = 0; ks < 16; ks++) {
        uint4 ah = *(const uint4*)(sm + apad(sA + ks * 32));
        #pragma unroll
        for (int nt = 0; nt < 4; nt++) {
            uint2 bv = Bfr[((wc * 4 + nt) * 16 + ks) * 32 + ln];
            mma_bf16(acc[nt], ah.x, ah.y, ah.z, ah.w, bv.x, bv.y);
        }
    }
}
// fusion chunk: 3-pass split bf16, B slots = uint4
static __device__ __forceinline__ void chunk_mma_f(const unsigned char* sm,
                                                   int wr, int wc, int ln, float acc[4][4]) {
    const uint4* Bfr = (const uint4*)(sm + OFF_B);
    const int sA = wr * 512 + ln;
    #pragma unroll
    for (int ks = 0; ks < 16; ks++) {
        int s = sA + ks * 32;
        uint4 ah = *(const uint4*)(sm + apad(s));
        uint4 al = *(const uint4*)(sm + OFF_AL + apad(s));
        #pragma unroll
        for (int nt = 0; nt < 4; nt++) {
            uint4 bv = Bfr[((wc * 4 + nt) * 16 + ks) * 32 + ln];
            mma_bf16(acc[nt], ah.x, ah.y, ah.z, ah.w, bv.x, bv.y);
            mma_bf16(acc[nt], ah.x, ah.y, ah.z, ah.w, bv.z, bv.w);
            mma_bf16(acc[nt], al.x, al.y, al.z, al.w, bv.x, bv.y);
        }
    }
}

__global__ void __launch_bounds__(512, 1) k_main(
    const float* __restrict__ img, const float* __restrict__ mem, const float* __restrict__ fb)
{
    extern __shared__ unsigned char sm[];
    const int t  = threadIdx.x;
    const int b  = blockIdx.x >> 5;
    const int p0 = (blockIdx.x & 31) * 128;
    const int w  = t >> 5;
    const int ln = t & 31;
    const int wr = w >> 1;
    const int wc = w & 1;

    float* A0s = (float*)(sm + OFF_SM);
    float* A1s = (float*)(sm + OFF_SM + 512);
    int*   I0s = (int*)  (sm + OFF_SM + 1024);
    int*   I1s = (int*)  (sm + OFF_SM + 1536);
    float* bS  = (float*)(sm + OFF_SM + 2048);
    int*   cnd = (int*)  (sm + OFF_SM + 3072);   // [128 px][8 cand]

    uint4 st[8];
    uint4* Bd = (uint4*)(sm + OFF_B);

    // LDG chunk 0 (score, 32KB) — overlaps with A staging below
    {
        const uint4* src = (const uint4*)g_memB;
        #pragma unroll
        for (int i = 0; i < 4; i++) st[i] = src[t + i * 512];
    }

    // ---- stage A: split bf16 h/l into padded fragment layout ----
    {
        const float* ib = img + (size_t)b * C_ * HW_ + p0;
        #pragma unroll
        for (int u0 = 0; u0 < 2; u0++) {
            int u = t + u0 * 512;
            int rp = u & 63, ks = u >> 6;
            int pxl = (rp >> 3) * 16 + (rp & 7);
            const float* ibc = ib + (size_t)(ks * 16) * HW_;
            unsigned short hlo[16], llo[16], hhi[16], lhi[16];
            #pragma unroll
            for (int kin = 0; kin < 16; kin++) {
                split_bf16(ibc[(size_t)kin * HW_ + pxl],     hlo[kin], llo[kin]);
                split_bf16(ibc[(size_t)kin * HW_ + pxl + 8], hhi[kin], lhi[kin]);
            }
            int s0 = ((rp >> 3) * 16 + ks) * 32 + (rp & 7) * 4;
            #pragma unroll
            for (int j = 0; j < 4; j++) {
                uint32_t ap = apad(s0 + j);
                *(uint4*)(sm + ap) =
                    make_uint4(pk(hlo[2*j], hlo[2*j+1]), pk(hhi[2*j], hhi[2*j+1]),
                               pk(hlo[8+2*j], hlo[8+2*j+1]), pk(hhi[8+2*j], hhi[8+2*j+1]));
                *(uint4*)(sm + OFF_AL + ap) =
                    make_uint4(pk(llo[2*j], llo[2*j+1]), pk(lhi[2*j], lhi[2*j+1]),
                               pk(llo[8+2*j], llo[8+2*j+1]), pk(lhi[8+2*j], lhi[8+2*j+1]));
            }
        }
    }
    if (t < 256) bS[t] = fb[t];

    // STS chunk 0
    #pragma unroll
    for (int i = 0; i < 4; i++) Bd[t + i * 512] = st[i];
    __syncthreads();

    // per-(lane,wc) top-4 candidates, 2 pixel slots
    float tv[2][4];
    int   ti[2][4];
    #pragma unroll
    for (int s = 0; s < 2; s++)
        #pragma unroll
        for (int j = 0; j < 4; j++) { tv[s][j] = -3.402823466e38f; ti[s][j] = 0; }

    for (int n = 0; n < NCHUNK; n++) {
        float acc[4][4];
        #pragma unroll
        for (int nt = 0; nt < 4; nt++)
            #pragma unroll
            for (int q = 0; q < 4; q++) acc[nt][q] = 0.f;

        if (n < 8) chunk_mma_s(sm, wr, wc, ln, acc);
        else       chunk_mma_f(sm, wr, wc, ln, acc);

        // prefetch B(n+1) into regs — B(n) in smem is dead after the MMA;
        // LDG latency is covered by the epilogue below. Short register liveness.
        {
            int np = n + 1;
            if (np < 8) {
                const uint4* src = (const uint4*)(g_memB + np * 32768);
                #pragma unroll
                for (int i = 0; i < 4; i++) st[i] = src[t + i * 512];
            } else if (np < NCHUNK) {
                const uint4* src = (const uint4*)(g_fwB + (b * 4 + (np - 8)) * 65536);
                #pragma unroll
                for (int i = 0; i < 8; i++) st[i] = src[t + i * 512];
            }
        }

        if (n < 8) {
            // chunk-local top-2 per slot, then merge into persistent top-4
            #pragma unroll
            for (int s = 0; s < 2; s++) {
                float cv0 = -3.402823466e38f, cv1 = -3.402823466e38f;
                int ci0 = 0, ci1 = 0;
                #pragma unroll
                for (int nt = 0; nt < 4; nt++) {
                    int mi = n * 64 + (wc * 4 + nt) * 8 + (ln & 3) * 2;
                    UPD2(acc[nt][s * 2 + 0], mi);
                    UPD2(acc[nt][s * 2 + 1], mi + 1);
                }
                ins4(tv[s], ti[s], cv0, ci0);
                ins4(tv[s], ti[s], cv1, ci1);
            }
            if (n == 7) {
                // merge top-4 across the 4 lanes sharing each pixel (same wc), publish candidates
                #pragma unroll
                for (int s = 0; s < 2; s++) {
                    #pragma unroll
                    for (int d = 1; d <= 2; d <<= 1) {
                        float pv[4]; int pi[4];
                        #pragma unroll
                        for (int j = 0; j < 4; j++) {
                            pv[j] = __shfl_xor_sync(0xFFFFFFFFu, tv[s][j], d);
                            pi[j] = __shfl_xor_sync(0xFFFFFFFFu, ti[s][j], d);
                        }
                        #pragma unroll
                        for (int j = 0; j < 4; j++) ins4(tv[s], ti[s], pv[j], pi[j]);
                    }
                    if ((ln & 3) == 0) {
                        int px = wr * 16 + s * 8 + (ln >> 2);
                        int* cp = cnd + px * 8 + wc * 4;
                        cp[0] = ti[s][0]; cp[1] = ti[s][1]; cp[2] = ti[s][2]; cp[3] = ti[s][3];
                    }
                }
            }
        } else {
            // fusion epilogue
            int oc0 = (n - 8) * 64;
            #pragma unroll
            for (int hf = 0; hf < 2; hf++) {
                int r = wr * 16 + hf * 8 + (ln >> 2);
                float a0 = A0s[r], a1 = A1s[r];
                const float* P0 = g_P + (size_t)I0s[r] * C_ + oc0;
                const float* P1 = g_P + (size_t)I1s[r] * C_ + oc0;
                float* xo = g_x + ((size_t)b * C_ + oc0) * HW_ + p0 + r;
                #pragma unroll
                for (int nt = 0; nt < 4; nt++) {
                    int ocl = wc * 32 + nt * 8 + (ln & 3) * 2;
                    float2 q0 = *(const float2*)(P0 + ocl);
                    float2 q1 = *(const float2*)(P1 + ocl);
                    float vx = acc[nt][hf * 2 + 0] + a0 * q0.x + a1 * q1.x + bS[oc0 + ocl];
                    float vy = acc[nt][hf * 2 + 1] + a0 * q0.y + a1 * q1.y + bS[oc0 + ocl + 1];
                    vx = (vx > 0.f) ? vx : 0.2f * vx;
                    vy = (vy > 0.f) ? vy : 0.2f * vy;
                    xo[(size_t)ocl * HW_] = vx;
                    xo[(size_t)(ocl + 1) * HW_] = vy;
                }
            }
        }
        __syncthreads();   // everyone done reading B(n) / writing cnd

        // stage B(n+1) from regs
        if (n < NCHUNK - 1) {
            if (n + 1 < 8) {
                #pragma unroll
                for (int i = 0; i < 4; i++) Bd[t + i * 512] = st[i];
            } else {
                #pragma unroll
                for (int i = 0; i < 8; i++) Bd[t + i * 512] = st[i];
            }
        }
        __syncthreads();   // B(n+1) ready

        if (n == 7) {
            // ---- rescore: warp w owns pixels [8w, 8w+8); lanes split the 256-c dot.
            //      8 candidates per pixel, processed in two groups of 4 (reg pressure). ----
            const int ks2 = ln >> 1, h = ln & 1;
            const int pxb = w * 8;
            #pragma unroll 1
            for (int pi = 0; pi < 8; pi++) {
                int px = pxb + pi;
                int mtg = px >> 4, r = px & 15;
                int sb = (mtg * 16 + ks2) * 32 + (r & 7) * 4;
                uint32_t wo = (uint32_t)((h * 2 + (r >> 3)) * 4);
                float aev[4], aov[4];
                #pragma unroll
                for (int q = 0; q < 4; q++) {
                    uint32_t ap = apad(sb + q) + wo;
                    uint32_t wh = *(const uint32_t*)(sm + ap);
                    uint32_t wl = *(const uint32_t*)(sm + OFF_AL + ap);
                    aev[q] = __uint_as_float(wh << 16) + __uint_as_float(wl << 16);
                    aov[q] = __uint_as_float(wh & 0xFFFF0000u) + __uint_as_float(wl & 0xFFFF0000u);
                }
                const int* cp = cnd + px * 8;
                float t0 = -3.402823466e38f, t1 = -3.402823466e38f;
                int   e0 = 0, e1 = 0;
                #pragma unroll 1
                for (int g = 0; g < 2; g++) {
                    int   mi[4];
                    float s[4];
                    #pragma unroll
                    for (int j = 0; j < 4; j++) {
                        mi[j] = cp[g * 4 + j];
                        const float4* rp = (const float4*)(mem + (size_t)mi[j] * C_ + ln * 8);
                        float4 b0 = rp[0], b1 = rp[1];
                        s[j] = aev[0] * b0.x + aov[0] * b0.y + aev[1] * b0.z + aov[1] * b0.w
                             + aev[2] * b1.x + aov[2] * b1.y + aev[3] * b1.z + aov[3] * b1.w;
                    }
                    #pragma unroll
                    for (int d = 16; d; d >>= 1)
                        #pragma unroll
                        for (int j = 0; j < 4; j++)
                            s[j] += __shfl_xor_sync(0xFFFFFFFFu, s[j], d);
                    #pragma unroll
                    for (int j = 0; j < 4; j++) {
                        if (better(s[j], mi[j], t0, e0)) { t1 = t0; e1 = e0; t0 = s[j]; e0 = mi[j]; }
                        else if (better(s[j], mi[j], t1, e1)) { t1 = s[j]; e1 = mi[j]; }
                    }
                }
                if (ln == 0) {
                    float e = expf(t1 - t0);
                    float a0 = 1.f / (1.f + e);
                    A0s[px] = a0; A1s[px] = e * a0; I0s[px] = e0; I1s[px] = e1;
                }
            }
            __syncthreads();
        }
    }
}

// ---------------- K4: depthwise dilated 3x3 (d=2) + bias + leaky ----------------
__global__ void k_dw(const float* __restrict__ dw, const float* __restrict__ db,
                     float* __restrict__ out) {
    __shared__ float sx[4096];
    __shared__ float w[9];
    int bc = blockIdx.x;
    int c = bc & 255;
    int t = threadIdx.x;
    const float4* x4 = (const float4*)(g_x + (size_t)bc * HW_);
    float4* s4 = (float4*)sx;
    for (int i = t; i < 1024; i += 256) s4[i] = x4[i];
    if (t < 9) w[t] = dw[c * 9 + t];
    __syncthreads();
    float bias = db[c];
    for (int p = t; p < 4096; p += 256) {
        int y = p >> 6, x = p & 63;
        float s = bias;
        #pragma unroll
        for (int ky = 0; ky < 3; ky++) {
            int iy = y + 2 * ky - 2;
            if ((unsigned)iy < 64u) {
                #pragma unroll
                for (int kx = 0; kx < 3; kx++) {
                    int ix = x + 2 * kx - 2;
                    if ((unsigned)ix < 64u) s += w[ky * 3 + kx] * sx[(iy << 6) + ix];
                }
            }
        }
        out[(size_t)bc * HW_ + p] = (s > 0.f) ? s : 0.2f * s;
    }
}

extern "C" void kernel_launch(void* const* d_in, const int* in_sizes, int n_in,
                              void* d_out, int out_size) {
    const float* img = (const float*)d_in[0];
    const float* mem = (const float*)d_in[1];
    const float* fw  = (const float*)d_in[2];
    const float* fb  = (const float*)d_in[3];
    const float* dw  = (const float*)d_in[4];
    const float* db  = (const float*)d_in[5];
    float* out = (float*)d_out;

    cudaFuncSetAttribute(k_main, cudaFuncAttributeMaxDynamicSharedMemorySize, SMEM_MAIN);

    k_mean<<<B_ * C_, 256>>>(img);
    k_prep<<<32, 256>>>(mem);
    k_pmat<<<M_, 256>>>(mem, fw);
    k_gsc<<<B_, 512>>>(mem);
    k_gacc<<<B_ * 8, 256>>>(mem);
    k_prepw<<<128, 256>>>(fw);
    k_main<<<B_ * (HW_ / 128), 512, SMEM_MAIN>>>(img, mem, fb);
    k_dw<<<B_ * C_, 256>>>(dw, db, out);
}